// round 2
// baseline (speedup 1.0000x reference)
#include <cuda_runtime.h>
#include <math.h>

#define D_MODEL 768
#define VOCAB   32128
#define NTOK    2048          // B*S = 4*512

#define BM 128
#define BN 128
#define BK 16
#define SSTR 17               // smem row stride (pad to kill bank conflicts)

// Scratch (no allocations allowed -> device globals)
__device__ float g_Hn[(size_t)NTOK * D_MODEL];
__device__ float g_nll[NTOK];
__device__ float g_cnt[NTOK];

__device__ __forceinline__ unsigned f2tf32(float x) {
    unsigned r;
    asm("cvt.rna.tf32.f32 %0, %1;" : "=r"(r) : "f"(x));
    return r;
}

// ---------------------------------------------------------------------------
// 1) T5 RMSNorm: h = x * rsqrt(mean(x^2) + eps) * w   -> g_Hn
// ---------------------------------------------------------------------------
__global__ void rmsnorm_kernel(const float* __restrict__ x,
                               const float* __restrict__ w) {
    const int row = blockIdx.x;
    const int tid = threadIdx.x;
    const float* xr = x + (size_t)row * D_MODEL;

    float ssq = 0.f;
    for (int i = tid; i < D_MODEL; i += 256) { float v = xr[i]; ssq += v * v; }

    __shared__ float red[256];
    red[tid] = ssq; __syncthreads();
    #pragma unroll
    for (int s = 128; s > 0; s >>= 1) {
        if (tid < s) red[tid] += red[tid + s];
        __syncthreads();
    }
    const float inv = rsqrtf(red[0] * (1.0f / D_MODEL) + 1e-6f);

    for (int i = tid; i < D_MODEL; i += 256)
        g_Hn[(size_t)row * D_MODEL + i] = xr[i] * inv * w[i];
}

// ---------------------------------------------------------------------------
// 2) GEMM: C[m, v] = sum_k Hn[m,k] * W[v,k]   (both row-major, K contiguous)
//    TF32 mma.sync m16n8k8, 128x128 block tile, BK=16, double-buffered smem.
//    N = 251*128 and M = 16*128 exactly -> no bounds checks.
// ---------------------------------------------------------------------------
__global__ void __launch_bounds__(256)
gemm_kernel(const float* __restrict__ W, float* __restrict__ C) {
    __shared__ unsigned As[2][BM * SSTR];
    __shared__ unsigned Bs[2][BN * SSTR];

    const int tid  = threadIdx.x;
    const int lane = tid & 31;
    const int warp = tid >> 5;
    const int gid  = lane >> 2;   // group id 0..7
    const int tig  = lane & 3;    // thread in group 0..3
    const int wm   = warp >> 2;   // 0..1  (64 rows each)
    const int wn   = warp & 3;    // 0..3  (32 cols each)

    const size_t bm = (size_t)blockIdx.y * BM;
    const size_t bn = (size_t)blockIdx.x * BN;
    const float* A = g_Hn;

    float acc[4][4][4];
    #pragma unroll
    for (int i = 0; i < 4; i++)
        #pragma unroll
        for (int j = 0; j < 4; j++)
            #pragma unroll
            for (int k = 0; k < 4; k++) acc[i][j][k] = 0.f;

    // Per-thread global-load coords: 128x16 tile = 512 float4; 2 per thread.
    const int r0 = tid >> 2;            // rows r0 and r0+64
    const int c0 = (tid & 3) * 4;       // col within BK (float index)

    float4 sa0, sa1, sb0, sb1;

    // Prologue: load k-tile 0
    sa0 = *(const float4*)(A + (bm + r0)      * D_MODEL + c0);
    sa1 = *(const float4*)(A + (bm + r0 + 64) * D_MODEL + c0);
    sb0 = *(const float4*)(W + (bn + r0)      * D_MODEL + c0);
    sb1 = *(const float4*)(W + (bn + r0 + 64) * D_MODEL + c0);
    {
        unsigned* p;
        p = &As[0][r0 * SSTR + c0];
        p[0]=f2tf32(sa0.x); p[1]=f2tf32(sa0.y); p[2]=f2tf32(sa0.z); p[3]=f2tf32(sa0.w);
        p = &As[0][(r0 + 64) * SSTR + c0];
        p[0]=f2tf32(sa1.x); p[1]=f2tf32(sa1.y); p[2]=f2tf32(sa1.z); p[3]=f2tf32(sa1.w);
        p = &Bs[0][r0 * SSTR + c0];
        p[0]=f2tf32(sb0.x); p[1]=f2tf32(sb0.y); p[2]=f2tf32(sb0.z); p[3]=f2tf32(sb0.w);
        p = &Bs[0][(r0 + 64) * SSTR + c0];
        p[0]=f2tf32(sb1.x); p[1]=f2tf32(sb1.y); p[2]=f2tf32(sb1.z); p[3]=f2tf32(sb1.w);
    }
    __syncthreads();

    const int NKT = D_MODEL / BK;   // 48
    for (int kt = 0; kt < NKT; ++kt) {
        const int buf = kt & 1;

        // Prefetch next k-tile into registers (hides LDG under MMA)
        if (kt + 1 < NKT) {
            const int ko = (kt + 1) * BK + c0;
            sa0 = *(const float4*)(A + (bm + r0)      * D_MODEL + ko);
            sa1 = *(const float4*)(A + (bm + r0 + 64) * D_MODEL + ko);
            sb0 = *(const float4*)(W + (bn + r0)      * D_MODEL + ko);
            sb1 = *(const float4*)(W + (bn + r0 + 64) * D_MODEL + ko);
        }

        // Compute 2 k-steps of 8
        #pragma unroll
        for (int ks = 0; ks < 2; ++ks) {
            unsigned a[4][4], b[4][2];
            #pragma unroll
            for (int mt = 0; mt < 4; ++mt) {
                const int r = wm * 64 + mt * 16 + gid;
                const int c = ks * 8 + tig;
                a[mt][0] = As[buf][r * SSTR + c];
                a[mt][1] = As[buf][(r + 8) * SSTR + c];
                a[mt][2] = As[buf][r * SSTR + c + 4];
                a[mt][3] = As[buf][(r + 8) * SSTR + c + 4];
            }
            #pragma unroll
            for (int nt = 0; nt < 4; ++nt) {
                const int n = wn * 32 + nt * 8 + gid;
                const int k = ks * 8 + tig;
                b[nt][0] = Bs[buf][n * SSTR + k];
                b[nt][1] = Bs[buf][n * SSTR + k + 4];
            }
            #pragma unroll
            for (int mt = 0; mt < 4; ++mt)
                #pragma unroll
                for (int nt = 0; nt < 4; ++nt) {
                    asm volatile(
                        "mma.sync.aligned.m16n8k8.row.col.f32.tf32.tf32.f32 "
                        "{%0,%1,%2,%3},{%4,%5,%6,%7},{%8,%9},{%0,%1,%2,%3};\n"
                        : "+f"(acc[mt][nt][0]), "+f"(acc[mt][nt][1]),
                          "+f"(acc[mt][nt][2]), "+f"(acc[mt][nt][3])
                        : "r"(a[mt][0]), "r"(a[mt][1]), "r"(a[mt][2]), "r"(a[mt][3]),
                          "r"(b[nt][0]), "r"(b[nt][1]));
                }
        }

        // Stage next tile into the other buffer
        if (kt + 1 < NKT) {
            const int nb = buf ^ 1;
            unsigned* p;
            p = &As[nb][r0 * SSTR + c0];
            p[0]=f2tf32(sa0.x); p[1]=f2tf32(sa0.y); p[2]=f2tf32(sa0.z); p[3]=f2tf32(sa0.w);
            p = &As[nb][(r0 + 64) * SSTR + c0];
            p[0]=f2tf32(sa1.x); p[1]=f2tf32(sa1.y); p[2]=f2tf32(sa1.z); p[3]=f2tf32(sa1.w);
            p = &Bs[nb][r0 * SSTR + c0];
            p[0]=f2tf32(sb0.x); p[1]=f2tf32(sb0.y); p[2]=f2tf32(sb0.z); p[3]=f2tf32(sb0.w);
            p = &Bs[nb][(r0 + 64) * SSTR + c0];
            p[0]=f2tf32(sb1.x); p[1]=f2tf32(sb1.y); p[2]=f2tf32(sb1.z); p[3]=f2tf32(sb1.w);
        }
        __syncthreads();
    }

    // Epilogue (scores base may be misaligned by 1 float -> scalar stores)
    #pragma unroll
    for (int mt = 0; mt < 4; ++mt) {
        const size_t r = bm + wm * 64 + mt * 16 + gid;
        #pragma unroll
        for (int nt = 0; nt < 4; ++nt) {
            const size_t c = bn + wn * 32 + nt * 8 + tig * 2;
            float* p0 = C + r * VOCAB + c;
            p0[0] = acc[mt][nt][0];
            p0[1] = acc[mt][nt][1];
            float* p1 = C + (r + 8) * VOCAB + c;
            p1[0] = acc[mt][nt][2];
            p1[1] = acc[mt][nt][3];
        }
    }
}

// ---------------------------------------------------------------------------
// 3) Per-row NLL:  nll = logsumexp(row) - logits[row, label]
//    NOTE: labels are int32 (JAX without x64 silently downcasts int64).
// ---------------------------------------------------------------------------
__global__ void loss_kernel(const float* __restrict__ logits,
                            const int* __restrict__ labels) {
    const int row = blockIdx.x;
    const int tid = threadIdx.x;
    const float* lr = logits + (size_t)row * VOCAB;

    __shared__ float red[256];

    float m = -1e30f;
    for (int i = tid; i < VOCAB; i += 256) m = fmaxf(m, lr[i]);
    red[tid] = m; __syncthreads();
    #pragma unroll
    for (int s = 128; s > 0; s >>= 1) {
        if (tid < s) red[tid] = fmaxf(red[tid], red[tid + s]);
        __syncthreads();
    }
    const float M = red[0];
    __syncthreads();

    float ssum = 0.f;
    for (int i = tid; i < VOCAB; i += 256) ssum += __expf(lr[i] - M);
    red[tid] = ssum; __syncthreads();
    #pragma unroll
    for (int s = 128; s > 0; s >>= 1) {
        if (tid < s) red[tid] += red[tid + s];
        __syncthreads();
    }

    if (tid == 0) {
        const int l = labels[row];
        if (l != -100) {
            const int sl = (l >= 0 && l < VOCAB) ? l : 0;
            g_nll[row] = logf(red[0]) + M - lr[sl];
            g_cnt[row] = 1.f;
        } else {
            g_nll[row] = 0.f;
            g_cnt[row] = 0.f;
        }
    }
}

// ---------------------------------------------------------------------------
// 4) Deterministic final reduction -> loss scalar
// ---------------------------------------------------------------------------
__global__ void finalize_kernel(float* __restrict__ loss_out) {
    if (loss_out == nullptr) return;
    __shared__ float rs[256], rc[256];
    const int tid = threadIdx.x;
    float s = 0.f, c = 0.f;
    for (int i = tid; i < NTOK; i += 256) { s += g_nll[i]; c += g_cnt[i]; }
    rs[tid] = s; rc[tid] = c; __syncthreads();
    #pragma unroll
    for (int st = 128; st > 0; st >>= 1) {
        if (tid < st) { rs[tid] += rs[tid + st]; rc[tid] += rc[tid + st]; }
        __syncthreads();
    }
    if (tid == 0) loss_out[0] = rs[0] / fmaxf(rc[0], 1.f);
}

// ---------------------------------------------------------------------------
extern "C" void kernel_launch(void* const* d_in, const int* in_sizes, int n_in,
                              void* d_out, int out_size) {
    const float* hidden = (const float*)d_in[0];   // [4,512,768] f32
    const int*   labels = (const int*)d_in[1];     // [4,512] int32 (JAX x64 off)
    const float* lnw    = (const float*)d_in[2];   // [768] f32
    const float* W      = (const float*)d_in[3];   // [32128,768] f32

    float* out = (float*)d_out;
    long long extra = (long long)out_size - (long long)NTOK * (long long)VOCAB;
    if (extra < 0) extra = 0;                // defensive
    float* scores   = out + extra;           // prediction_scores region
    float* loss_ptr = (extra >= 1) ? out : nullptr;

    rmsnorm_kernel<<<NTOK, 256>>>(hidden, lnw);

    dim3 grid(VOCAB / BN, NTOK / BM);        // (251, 16), exact tiling
    gemm_kernel<<<grid, 256>>>(W, scores);

    loss_kernel<<<NTOK, 256>>>(scores, labels);
    finalize_kernel<<<1, 256>>>(loss_ptr);
}

// round 4
// speedup vs baseline: 1.5125x; 1.5125x over previous
#include <cuda_runtime.h>
#include <math.h>
#include <stdint.h>

#define D_MODEL 768
#define VOCAB   32128
#define NTOK    2048
#define NTILES_N 251           // VOCAB / 128
#define BM 256
#define BN 128
#define BKF 32                 // k-floats per chunk
#define NCHUNK (D_MODEL / BKF) // 24
#define ASTR 36                // smem row stride in floats (conflict-free)
#define ABYTES (BM * ASTR * 4) // 36864
#define BBYTES (BN * ASTR * 4) // 18432
#define BUFB   (ABYTES + BBYTES)   // 55296
#define SMEM_TOTAL (3 * BUFB)      // 165888

// Scratch (static: no allocations allowed)
__device__ float g_Hn[(size_t)NTOK * D_MODEL];
__device__ float g_Wt[(size_t)VOCAB * D_MODEL];     // tf32-formatted W
__device__ float g_pmax[(size_t)NTOK * NTILES_N];
__device__ float g_psum[(size_t)NTOK * NTILES_N];
__device__ float g_nll[NTOK];
__device__ float g_cnt[NTOK];

__device__ __forceinline__ float f2tf32f(float x) {
    unsigned r;
    asm("cvt.rna.tf32.f32 %0, %1;" : "=r"(r) : "f"(x));
    return __uint_as_float(r);
}
__device__ __forceinline__ uint32_t smem_u32(const void* p) {
    return (uint32_t)__cvta_generic_to_shared(p);
}
__device__ __forceinline__ void cp16(uint32_t dst, const void* src) {
    asm volatile("cp.async.cg.shared.global [%0], [%1], 16;"
                 :: "r"(dst), "l"(src) : "memory");
}
#define CP_COMMIT() asm volatile("cp.async.commit_group;" ::: "memory")
#define CP_WAIT(n)  asm volatile("cp.async.wait_group %0;" :: "n"(n) : "memory")

// ---------------------------------------------------------------------------
// 1) Fused prep: blocks [0,2048) = RMSNorm -> g_Hn (tf32-formatted)
//                blocks [2048, ...) = convert W -> g_Wt
// ---------------------------------------------------------------------------
#define WCVT_BLOCKS 6028       // ceil(32128*768/16 / (256*4)) covers all float4s
__global__ void prep_kernel(const float* __restrict__ x,
                            const float* __restrict__ w,
                            const float* __restrict__ W) {
    const int tid = threadIdx.x;
    if (blockIdx.x < NTOK) {
        const int row = blockIdx.x;
        const float* xr = x + (size_t)row * D_MODEL;
        float ssq = 0.f;
        for (int i = tid; i < D_MODEL; i += 256) { float v = xr[i]; ssq += v * v; }
        __shared__ float red[256];
        red[tid] = ssq; __syncthreads();
        #pragma unroll
        for (int s = 128; s > 0; s >>= 1) {
            if (tid < s) red[tid] += red[tid + s];
            __syncthreads();
        }
        const float inv = rsqrtf(red[0] * (1.0f / D_MODEL) + 1e-6f);
        for (int i = tid; i < D_MODEL; i += 256)
            g_Hn[(size_t)row * D_MODEL + i] = f2tf32f(xr[i] * inv * w[i]);
    } else {
        const size_t nf4 = (size_t)VOCAB * D_MODEL / 4;   // 6168576
        const size_t base = ((size_t)(blockIdx.x - NTOK) * 256 + tid) * 4;
        const float4* src = (const float4*)W;
        float4* dst = (float4*)g_Wt;
        #pragma unroll
        for (int i = 0; i < 4; ++i) {
            const size_t idx = base / 4 + (size_t)i * WCVT_BLOCKS * 256;
            if (idx < nf4) {
                float4 v = src[idx];
                v.x = f2tf32f(v.x); v.y = f2tf32f(v.y);
                v.z = f2tf32f(v.z); v.w = f2tf32f(v.w);
                dst[idx] = v;
            }
        }
    }
}

// ---------------------------------------------------------------------------
// 2) GEMM (mma.sync tf32) 256x128 block tile, cp.async 3-stage, fused lse
// ---------------------------------------------------------------------------
__device__ __forceinline__ void stage_chunk(uint32_t sbuf, int kt,
                                            size_t bm, size_t bn, int tid) {
    const int row = tid >> 3;          // 0..31
    const int c16 = tid & 7;           // 16B unit
    #pragma unroll
    for (int i = 0; i < 8; ++i) {      // A: 256 rows
        const int r = row + i * 32;
        cp16(sbuf + (uint32_t)(r * (ASTR * 4) + c16 * 16),
             g_Hn + (bm + r) * D_MODEL + kt * BKF + c16 * 4);
    }
    #pragma unroll
    for (int i = 0; i < 4; ++i) {      // B: 128 rows
        const int r = row + i * 32;
        cp16(sbuf + ABYTES + (uint32_t)(r * (ASTR * 4) + c16 * 16),
             g_Wt + (bn + r) * D_MODEL + kt * BKF + c16 * 4);
    }
}

__global__ void __launch_bounds__(256)
gemm_kernel(float* __restrict__ C) {
    extern __shared__ float smem[];
    const uint32_t sb = smem_u32(smem);

    const int tid  = threadIdx.x;
    const int wid  = tid >> 5;
    const int lane = tid & 31;
    const int gid  = lane >> 2;
    const int tig  = lane & 3;

    const size_t bm = (size_t)blockIdx.y * BM;
    const size_t bn = (size_t)blockIdx.x * BN;

    float acc[2][16][4];
    #pragma unroll
    for (int mt = 0; mt < 2; ++mt)
        #pragma unroll
        for (int nt = 0; nt < 16; ++nt)
            #pragma unroll
            for (int k = 0; k < 4; ++k) acc[mt][nt][k] = 0.f;

    stage_chunk(sb, 0, bm, bn, tid); CP_COMMIT();
    stage_chunk(sb + BUFB, 1, bm, bn, tid); CP_COMMIT();

    const float* Asm_base = smem;
    for (int kt = 0; kt < NCHUNK; ++kt) {
        if (kt < NCHUNK - 1) { CP_WAIT(1); } else { CP_WAIT(0); }
        __syncthreads();

        if (kt + 2 < NCHUNK) {
            stage_chunk(sb + ((kt + 2) % 3) * BUFB, kt + 2, bm, bn, tid);
            CP_COMMIT();
        }

        const float* As = Asm_base + ((kt % 3) * BUFB) / 4;
        const float* Bs = As + ABYTES / 4;
        const int rbase = wid * 32 + gid;

        #pragma unroll
        for (int ks = 0; ks < 4; ++ks) {
            const int kc = ks * 8 + tig;
            unsigned a[2][4];
            #pragma unroll
            for (int mt = 0; mt < 2; ++mt) {
                const int r = rbase + mt * 16;
                a[mt][0] = __float_as_uint(As[r * ASTR + kc]);
                a[mt][1] = __float_as_uint(As[(r + 8) * ASTR + kc]);
                a[mt][2] = __float_as_uint(As[r * ASTR + kc + 4]);
                a[mt][3] = __float_as_uint(As[(r + 8) * ASTR + kc + 4]);
            }
            #pragma unroll
            for (int nt = 0; nt < 16; ++nt) {
                const int n = nt * 8 + gid;
                const unsigned b0 = __float_as_uint(Bs[n * ASTR + kc]);
                const unsigned b1 = __float_as_uint(Bs[n * ASTR + kc + 4]);
                #pragma unroll
                for (int mt = 0; mt < 2; ++mt) {
                    asm volatile(
                        "mma.sync.aligned.m16n8k8.row.col.f32.tf32.tf32.f32 "
                        "{%0,%1,%2,%3},{%4,%5,%6,%7},{%8,%9},{%0,%1,%2,%3};\n"
                        : "+f"(acc[mt][nt][0]), "+f"(acc[mt][nt][1]),
                          "+f"(acc[mt][nt][2]), "+f"(acc[mt][nt][3])
                        : "r"(a[mt][0]), "r"(a[mt][1]), "r"(a[mt][2]), "r"(a[mt][3]),
                          "r"(b0), "r"(b1));
                }
            }
        }
        __syncthreads();
    }

    // Epilogue: store C + fused per-row logsumexp partials over these 128 cols.
    #pragma unroll
    for (int mt = 0; mt < 2; ++mt) {
        #pragma unroll
        for (int h = 0; h < 2; ++h) {
            const size_t r = bm + wid * 32 + mt * 16 + gid + h * 8;
            float* cr = C + r * VOCAB + bn + tig * 2;
            float m = -1e30f;
            #pragma unroll
            for (int nt = 0; nt < 16; ++nt) {
                const float v0 = acc[mt][nt][2 * h];
                const float v1 = acc[mt][nt][2 * h + 1];
                cr[nt * 8]     = v0;
                cr[nt * 8 + 1] = v1;
                m = fmaxf(m, fmaxf(v0, v1));
            }
            float s = 0.f;
            #pragma unroll
            for (int nt = 0; nt < 16; ++nt) {
                s += __expf(acc[mt][nt][2 * h] - m);
                s += __expf(acc[mt][nt][2 * h + 1] - m);
            }
            // merge (m,s) across the 4 threads (tig 0..3) holding this row
            #pragma unroll
            for (int d = 1; d < 4; d <<= 1) {
                const float om = __shfl_xor_sync(0xFFFFFFFFu, m, d);
                const float os = __shfl_xor_sync(0xFFFFFFFFu, s, d);
                const float nm = fmaxf(m, om);
                s = s * __expf(m - nm) + os * __expf(om - nm);
                m = nm;
            }
            if (tig == 0) {
                g_pmax[r * NTILES_N + blockIdx.x] = m;
                g_psum[r * NTILES_N + blockIdx.x] = s;
            }
        }
    }
}

// ---------------------------------------------------------------------------
// 3) Combine partials -> per-row NLL
// ---------------------------------------------------------------------------
__global__ void combine_loss_kernel(const float* __restrict__ scores,
                                    const int* __restrict__ labels) {
    const int row = blockIdx.x;
    const int tid = threadIdx.x;
    __shared__ float red[256];

    float pm = -1e30f;
    if (tid < NTILES_N) pm = g_pmax[(size_t)row * NTILES_N + tid];
    red[tid] = pm; __syncthreads();
    #pragma unroll
    for (int s = 128; s > 0; s >>= 1) {
        if (tid < s) red[tid] = fmaxf(red[tid], red[tid + s]);
        __syncthreads();
    }
    const float M = red[0];
    __syncthreads();

    float ps = 0.f;
    if (tid < NTILES_N)
        ps = g_psum[(size_t)row * NTILES_N + tid] * __expf(pm - M);
    red[tid] = ps; __syncthreads();
    #pragma unroll
    for (int s = 128; s > 0; s >>= 1) {
        if (tid < s) red[tid] += red[tid + s];
        __syncthreads();
    }

    if (tid == 0) {
        const int l = labels[row];
        if (l != -100) {
            const int sl = (l >= 0 && l < VOCAB) ? l : 0;
            g_nll[row] = logf(red[0]) + M - scores[(size_t)row * VOCAB + sl];
            g_cnt[row] = 1.f;
        } else {
            g_nll[row] = 0.f;
            g_cnt[row] = 0.f;
        }
    }
}

// ---------------------------------------------------------------------------
// 4) Deterministic final reduction
// ---------------------------------------------------------------------------
__global__ void finalize_kernel(float* __restrict__ loss_out) {
    if (loss_out == nullptr) return;
    __shared__ float rs[256], rc[256];
    const int tid = threadIdx.x;
    float s = 0.f, c = 0.f;
    for (int i = tid; i < NTOK; i += 256) { s += g_nll[i]; c += g_cnt[i]; }
    rs[tid] = s; rc[tid] = c; __syncthreads();
    #pragma unroll
    for (int st = 128; st > 0; st >>= 1) {
        if (tid < st) { rs[tid] += rs[tid + st]; rc[tid] += rc[tid + st]; }
        __syncthreads();
    }
    if (tid == 0) loss_out[0] = rs[0] / fmaxf(rc[0], 1.f);
}

// ---------------------------------------------------------------------------
extern "C" void kernel_launch(void* const* d_in, const int* in_sizes, int n_in,
                              void* d_out, int out_size) {
    const float* hidden = (const float*)d_in[0];
    const int*   labels = (const int*)d_in[1];
    const float* lnw    = (const float*)d_in[2];
    const float* W      = (const float*)d_in[3];

    float* out = (float*)d_out;
    long long extra = (long long)out_size - (long long)NTOK * (long long)VOCAB;
    if (extra < 0) extra = 0;
    float* scores   = out + extra;
    float* loss_ptr = (extra >= 1) ? out : nullptr;

    static int smem_set = 0;
    if (!smem_set) {
        cudaFuncSetAttribute(gemm_kernel,
                             cudaFuncAttributeMaxDynamicSharedMemorySize, SMEM_TOTAL);
        smem_set = 1;
    }

    prep_kernel<<<NTOK + WCVT_BLOCKS, 256>>>(hidden, lnw, W);
    gemm_kernel<<<dim3(NTILES_N, NTOK / BM), 256, SMEM_TOTAL>>>(scores);
    combine_loss_kernel<<<NTOK, 256>>>(scores, labels);
    finalize_kernel<<<1, 256>>>(loss_ptr);
}